// round 2
// baseline (speedup 1.0000x reference)
#include <cuda_runtime.h>
#include <cuda_fp16.h>

// ---------------------------------------------------------------------------
// Mipmapped texture sampling, GB300 — fp16 pyramid (32B/texel, HWC).
// Level i (i>=1) texel = 0.25 * 2x2 of base at y0 = y*2^i + 2^(i-1) - 1
// (exact algebra of align_corners=False bilinear downsample by 2^i).
// ---------------------------------------------------------------------------

#define NLEV 8

// total texels: 512^2+256^2+...+4^2 = 349,520 ; * 16 ch = 5,592,320 halves (11.2 MB)
__device__ __align__(16) __half g_pyr[5592320];

__constant__ int c_off[NLEV] = {
    0, 4194304, 5242880, 5505024, 5570560, 5586944, 5591040, 5592064
};

// ---------------------------------------------------------------------------
// Kernel 1: CHW (16,512,512) fp32 -> HWC fp16 level 0.
// One thread per pixel: 16 warp-coalesced plane reads, one 32B contiguous store.
// ---------------------------------------------------------------------------
__global__ void k_transpose(const float* __restrict__ tex) {
    int pix = blockIdx.x * blockDim.x + threadIdx.x;
    if (pix >= 512 * 512) return;
    const int plane = 512 * 512;
    __half h[16];
#pragma unroll
    for (int c = 0; c < 16; c++)
        h[c] = __float2half_rn(__ldg(&tex[c * plane + pix]));
    uint4* dst = reinterpret_cast<uint4*>(g_pyr) + pix * 2;
    dst[0] = *reinterpret_cast<const uint4*>(&h[0]);
    dst[1] = *reinterpret_cast<const uint4*>(&h[8]);
}

// ---------------------------------------------------------------------------
// Kernel 2: build levels 1..7 directly from level 0 (2x2 average).
// One thread per destination texel (87,376 threads), all 16 channels.
// ---------------------------------------------------------------------------
__global__ void k_mips() {
    int rem = blockIdx.x * blockDim.x + threadIdx.x;
    if (rem >= 87376) return;

    int l = 1;
#pragma unroll
    for (int i = 1; i < NLEV; i++) {
        int np = (512 >> i) * (512 >> i);
        if (rem < np) { l = i; break; }
        rem -= np;
    }
    int s  = 512 >> l;
    int x  = rem & (s - 1);
    int y  = rem >> (9 - l);
    int sc = 1 << l;
    int x0 = x * sc + (sc >> 1) - 1;
    int y0 = y * sc + (sc >> 1) - 1;

    const uint4* base = reinterpret_cast<const uint4*>(g_pyr);
    float acc[16];
#pragma unroll
    for (int i = 0; i < 16; i++) acc[i] = 0.0f;

#pragma unroll
    for (int dy = 0; dy < 2; dy++) {
#pragma unroll
        for (int dx = 0; dx < 2; dx++) {
            int pix = (y0 + dy) * 512 + (x0 + dx);
#pragma unroll
            for (int hseg = 0; hseg < 2; hseg++) {
                uint4 v = __ldg(&base[pix * 2 + hseg]);
                const __half2* h2 = reinterpret_cast<const __half2*>(&v);
#pragma unroll
                for (int i = 0; i < 4; i++) {
                    float2 f = __half22float2(h2[i]);
                    acc[hseg * 8 + 2 * i]     += f.x;
                    acc[hseg * 8 + 2 * i + 1] += f.y;
                }
            }
        }
    }

    __half r[16];
#pragma unroll
    for (int i = 0; i < 16; i++) r[i] = __float2half_rn(0.25f * acc[i]);
    uint4* dst = reinterpret_cast<uint4*>(g_pyr + c_off[l]) + (y * s + x) * 2;
    dst[0] = *reinterpret_cast<const uint4*>(&r[0]);
    dst[1] = *reinterpret_cast<const uint4*>(&r[8]);
}

// ---------------------------------------------------------------------------
// Kernel 3: sample. 2 threads per query, each owns 8 channels (one LDG.128
// per texel). Level-lerp folded into the 8 accumulate weights.
// ---------------------------------------------------------------------------
__device__ __forceinline__ void acc8(uint4 v, float w, float* a) {
    const __half2* h2 = reinterpret_cast<const __half2*>(&v);
#pragma unroll
    for (int i = 0; i < 4; i++) {
        float2 f = __half22float2(h2[i]);
        a[2 * i]     += w * f.x;
        a[2 * i + 1] += w * f.y;
    }
}

__device__ __forceinline__ void sample_level(int l, float gx, float gy, int t,
                                             float lw, float* acc) {
    int   s  = 512 >> l;
    float fs = (float)(s - 1);
    float x = fminf(fmaxf((gx + 1.0f) * 0.5f * fs, 0.0f), fs);
    float y = fminf(fmaxf((gy + 1.0f) * 0.5f * fs, 0.0f), fs);
    int x0 = (int)x;
    int y0 = (int)y;
    int x1 = min(x0 + 1, s - 1);
    int y1 = min(y0 + 1, s - 1);
    float fx = x - (float)x0;
    float fy = y - (float)y0;

    const uint4* b = reinterpret_cast<const uint4*>(g_pyr + c_off[l]);
    int r0 = y0 * s, r1 = y1 * s;
    uint4 v00 = __ldg(&b[(r0 + x0) * 2 + t]);
    uint4 v01 = __ldg(&b[(r0 + x1) * 2 + t]);
    uint4 v10 = __ldg(&b[(r1 + x0) * 2 + t]);
    uint4 v11 = __ldg(&b[(r1 + x1) * 2 + t]);

    acc8(v00, lw * (1.0f - fx) * (1.0f - fy), acc);
    acc8(v01, lw * fx * (1.0f - fy), acc);
    acc8(v10, lw * (1.0f - fx) * fy, acc);
    acc8(v11, lw * fx * fy, acc);
}

__global__ void k_sample(const float* __restrict__ uv,
                         const float* __restrict__ p,
                         float* __restrict__ out, int N) {
    int idx = blockIdx.x * blockDim.x + threadIdx.x;
    int q = idx >> 1;
    if (q >= N) return;
    int t = idx & 1;

    float u  = __ldg(&uv[2 * q]);
    float v  = __ldg(&uv[2 * q + 1]);
    float pp = __ldg(&p[q]);

    float lf = pp * (float)(NLEV - 1);
    int   l0 = (int)floorf(lf);
    l0 = max(0, min(l0, NLEV - 1));
    int   l1 = min(l0 + 1, NLEV - 1);
    float alpha = lf - (float)l0;

    float gx = 2.0f * u - 1.0f;
    float gy = 2.0f * v - 1.0f;

    float acc[8];
#pragma unroll
    for (int i = 0; i < 8; i++) acc[i] = 0.0f;

    sample_level(l0, gx, gy, t, 1.0f - alpha, acc);
    sample_level(l1, gx, gy, t, alpha, acc);

    // streaming stores: keep the 64MB output from evicting the pyramid in L2
    float4* o = reinterpret_cast<float4*>(out) + q * 4 + t * 2;
    __stcs(o,     *reinterpret_cast<const float4*>(&acc[0]));
    __stcs(o + 1, *reinterpret_cast<const float4*>(&acc[4]));
}

// ---------------------------------------------------------------------------
extern "C" void kernel_launch(void* const* d_in, const int* in_sizes, int n_in,
                              void* d_out, int out_size) {
    const float* uv  = (const float*)d_in[0];
    const float* p   = (const float*)d_in[1];
    const float* tex = (const float*)d_in[2];
    float* out = (float*)d_out;
    int N = in_sizes[1];          // number of queries (p element count)

    k_transpose<<<(512 * 512 + 255) / 256, 256>>>(tex);
    k_mips<<<(87376 + 255) / 256, 256>>>();
    int total = N * 2;
    k_sample<<<(total + 255) / 256, 256>>>(uv, p, out, N);
}

// round 5
// speedup vs baseline: 1.5659x; 1.5659x over previous
#include <cuda_runtime.h>
#include <cuda_fp16.h>

// ---------------------------------------------------------------------------
// Mipmapped texture sampling, GB300 — fp16 pyramid (32B/texel, HWC).
// Level i (i>=1) texel = 0.25 * 2x2 of base at y0 = y*2^i + 2^(i-1) - 1
// (exact algebra of align_corners=False bilinear downsample by 2^i).
// NO addressable local arrays anywhere — all state in named registers.
// ---------------------------------------------------------------------------

#define NLEV 8

__device__ __align__(16) __half g_pyr[5592320];

__constant__ int c_off[NLEV] = {
    0, 4194304, 5242880, 5505024, 5570560, 5586944, 5591040, 5592064
};

// scalar bitcasts (register-safe; only arrays get demoted to local mem)
__device__ __forceinline__ float2 u2f2(unsigned u) {
    return __half22float2(*reinterpret_cast<const __half2*>(&u));
}
__device__ __forceinline__ unsigned f2u(float a, float b) {
    __half2 h = __floats2half2_rn(a, b);
    return *reinterpret_cast<const unsigned*>(&h);
}

// ---------------------------------------------------------------------------
// Kernel 1: CHW (16,512,512) fp32 -> HWC fp16 level 0.
// 2 threads per pixel, plane-major t: warp loads are 128B-coalesced per plane.
// ---------------------------------------------------------------------------
__global__ void k_transpose(const float* __restrict__ tex) {
    int idx = blockIdx.x * blockDim.x + threadIdx.x;
    if (idx >= 2 * 512 * 512) return;
    int t   = idx >> 18;                 // 0: channels 0-7, 1: channels 8-15
    int pix = idx & (512 * 512 - 1);
    const int plane = 512 * 512;
    const float* base = tex + (8 * t) * plane + pix;

    float c0 = __ldg(base);
    float c1 = __ldg(base + plane);
    float c2 = __ldg(base + 2 * plane);
    float c3 = __ldg(base + 3 * plane);
    float c4 = __ldg(base + 4 * plane);
    float c5 = __ldg(base + 5 * plane);
    float c6 = __ldg(base + 6 * plane);
    float c7 = __ldg(base + 7 * plane);

    uint4 v;
    v.x = f2u(c0, c1);
    v.y = f2u(c2, c3);
    v.z = f2u(c4, c5);
    v.w = f2u(c6, c7);
    reinterpret_cast<uint4*>(g_pyr)[pix * 2 + t] = v;
}

// ---------------------------------------------------------------------------
// Kernel 2: levels 1..7 as direct 2x2 average of level 0.
// 2 threads per destination texel (8 channels each), register accumulators.
// ---------------------------------------------------------------------------
__global__ void k_mips() {
    int idx = blockIdx.x * blockDim.x + threadIdx.x;
    if (idx >= 2 * 87376) return;
    int t   = idx & 1;
    int rem = idx >> 1;

    int l = 1;
#pragma unroll
    for (int i = 1; i < NLEV; i++) {
        int np = (512 >> i) * (512 >> i);
        if (rem < np) { l = i; break; }
        rem -= np;
    }
    int s  = 512 >> l;
    int x  = rem & (s - 1);
    int y  = rem >> (9 - l);
    int sc = 1 << l;
    int x0 = x * sc + (sc >> 1) - 1;
    int y0 = y * sc + (sc >> 1) - 1;

    const uint4* base = reinterpret_cast<const uint4*>(g_pyr);
    uint4 va = __ldg(&base[(y0       * 512 + x0    ) * 2 + t]);
    uint4 vb = __ldg(&base[(y0       * 512 + x0 + 1) * 2 + t]);
    uint4 vc = __ldg(&base[((y0 + 1) * 512 + x0    ) * 2 + t]);
    uint4 vd = __ldg(&base[((y0 + 1) * 512 + x0 + 1) * 2 + t]);

    float4 A = make_float4(0.f, 0.f, 0.f, 0.f);
    float4 B = make_float4(0.f, 0.f, 0.f, 0.f);
#define ACC(V) {                                               \
        float2 f0 = u2f2(V.x); A.x += f0.x; A.y += f0.y;        \
        float2 f1 = u2f2(V.y); A.z += f1.x; A.w += f1.y;        \
        float2 f2 = u2f2(V.z); B.x += f2.x; B.y += f2.y;        \
        float2 f3 = u2f2(V.w); B.z += f3.x; B.w += f3.y; }
    ACC(va) ACC(vb) ACC(vc) ACC(vd)
#undef ACC

    uint4 r;
    r.x = f2u(0.25f * A.x, 0.25f * A.y);
    r.y = f2u(0.25f * A.z, 0.25f * A.w);
    r.z = f2u(0.25f * B.x, 0.25f * B.y);
    r.w = f2u(0.25f * B.z, 0.25f * B.w);
    reinterpret_cast<uint4*>(g_pyr + c_off[l])[(y * s + x) * 2 + t] = r;
}

// ---------------------------------------------------------------------------
// Kernel 3: sample. 2 threads/query, 8 channels each (one LDG.128 per texel).
// All 8 loads (both levels) issued before any accumulation (MLP=8).
// ---------------------------------------------------------------------------
__device__ __forceinline__ void lvl_setup(int l, float gx, float gy, int t, float lw,
        const uint4*& p00, const uint4*& p01, const uint4*& p10, const uint4*& p11,
        float& w00, float& w01, float& w10, float& w11) {
    int   s  = 512 >> l;
    float fs = (float)(s - 1);
    float x = fminf(fmaxf((gx + 1.0f) * 0.5f * fs, 0.0f), fs);
    float y = fminf(fmaxf((gy + 1.0f) * 0.5f * fs, 0.0f), fs);
    int x0 = (int)x;
    int y0 = (int)y;
    int x1 = min(x0 + 1, s - 1);
    int y1 = min(y0 + 1, s - 1);
    float fx = x - (float)x0;
    float fy = y - (float)y0;

    const uint4* b = reinterpret_cast<const uint4*>(g_pyr + c_off[l]);
    int r0 = y0 * s, r1 = y1 * s;
    p00 = &b[(r0 + x0) * 2 + t];
    p01 = &b[(r0 + x1) * 2 + t];
    p10 = &b[(r1 + x0) * 2 + t];
    p11 = &b[(r1 + x1) * 2 + t];
    w00 = lw * (1.0f - fx) * (1.0f - fy);
    w01 = lw * fx * (1.0f - fy);
    w10 = lw * (1.0f - fx) * fy;
    w11 = lw * fx * fy;
}

__global__ void k_sample(const float* __restrict__ uv,
                         const float* __restrict__ p,
                         float* __restrict__ out, int N) {
    int idx = blockIdx.x * blockDim.x + threadIdx.x;
    int q = idx >> 1;
    if (q >= N) return;
    int t = idx & 1;

    float u  = __ldg(&uv[2 * q]);
    float v  = __ldg(&uv[2 * q + 1]);
    float pp = __ldg(&p[q]);

    float lf = pp * (float)(NLEV - 1);
    int   l0 = min((int)lf, NLEV - 1);          // pp >= 0 -> trunc == floor
    int   l1 = min(l0 + 1, NLEV - 1);
    float alpha = lf - (float)l0;

    float gx = 2.0f * u - 1.0f;
    float gy = 2.0f * v - 1.0f;

    const uint4 *a00, *a01, *a10, *a11, *b00, *b01, *b10, *b11;
    float wa00, wa01, wa10, wa11, wb00, wb01, wb10, wb11;
    lvl_setup(l0, gx, gy, t, 1.0f - alpha, a00, a01, a10, a11, wa00, wa01, wa10, wa11);
    lvl_setup(l1, gx, gy, t, alpha,        b00, b01, b10, b11, wb00, wb01, wb10, wb11);

    // batch all 8 texel loads
    uint4 va0 = __ldg(a00);
    uint4 va1 = __ldg(a01);
    uint4 va2 = __ldg(a10);
    uint4 va3 = __ldg(a11);
    uint4 vb0 = __ldg(b00);
    uint4 vb1 = __ldg(b01);
    uint4 vb2 = __ldg(b10);
    uint4 vb3 = __ldg(b11);

    float4 A = make_float4(0.f, 0.f, 0.f, 0.f);
    float4 B = make_float4(0.f, 0.f, 0.f, 0.f);
#define ACC(V, W) {                                                  \
        float2 f0 = u2f2(V.x); A.x += (W) * f0.x; A.y += (W) * f0.y;  \
        float2 f1 = u2f2(V.y); A.z += (W) * f1.x; A.w += (W) * f1.y;  \
        float2 f2 = u2f2(V.z); B.x += (W) * f2.x; B.y += (W) * f2.y;  \
        float2 f3 = u2f2(V.w); B.z += (W) * f3.x; B.w += (W) * f3.y; }
    ACC(va0, wa00) ACC(va1, wa01) ACC(va2, wa10) ACC(va3, wa11)
    ACC(vb0, wb00) ACC(vb1, wb01) ACC(vb2, wb10) ACC(vb3, wb11)
#undef ACC

    // streaming stores: keep the 64MB output from evicting the pyramid in L2
    float4* o = reinterpret_cast<float4*>(out) + q * 4 + t * 2;
    __stcs(o,     A);
    __stcs(o + 1, B);
}

// ---------------------------------------------------------------------------
extern "C" void kernel_launch(void* const* d_in, const int* in_sizes, int n_in,
                              void* d_out, int out_size) {
    const float* uv  = (const float*)d_in[0];
    const float* p   = (const float*)d_in[1];
    const float* tex = (const float*)d_in[2];
    float* out = (float*)d_out;
    int N = in_sizes[1];          // number of queries (p element count)

    k_transpose<<<(2 * 512 * 512) / 256, 256>>>(tex);
    k_mips<<<(2 * 87376 + 255) / 256, 256>>>();
    int total = N * 2;
    k_sample<<<(total + 255) / 256, 256>>>(uv, p, out, N);
}